// round 1
// baseline (speedup 1.0000x reference)
#include <cuda_runtime.h>
#include <math.h>

#define Bb   2
#define Ss   2048
#define Dd   1024
#define NH   16
#define NKV  4
#define HD   64
#define MM   (Bb * Ss)        // 4096 rows
#define REP  (NH / NKV)       // 4

// Scratch (no allocation allowed): q/k/v post-projection, o = attention output
__device__ float g_q[MM * NH * HD];    // [4096, 1024]
__device__ float g_k[MM * NKV * HD];   // [4096, 256]
__device__ float g_v[MM * NKV * HD];   // [4096, 256]
__device__ float g_o[MM * NH * HD];    // [4096, 1024]

// ---------------------------------------------------------------------------
// SGEMM: C[M,N] = A[M,K] * W[N,K]^T   (torch Linear form)
// 128x128 tile, BK=8, 256 threads, 8x8 per-thread microtile.
// ---------------------------------------------------------------------------
__global__ __launch_bounds__(256) void sgemm_nt(const float* __restrict__ A,
                                                const float* __restrict__ W,
                                                float* __restrict__ C,
                                                int M, int N, int K) {
    __shared__ float As[8][132];
    __shared__ float Bs[8][132];
    const int tid = threadIdx.x;
    const int tx = tid & 15, ty = tid >> 4;
    const int m0 = blockIdx.y * 128, n0 = blockIdx.x * 128;
    const int lrow = tid >> 1;
    const int lk   = (tid & 1) << 2;
    const float* Ap = A + (size_t)(m0 + lrow) * K + lk;
    const float* Wp = W + (size_t)(n0 + lrow) * K + lk;

    float acc[8][8];
#pragma unroll
    for (int i = 0; i < 8; i++)
#pragma unroll
        for (int j = 0; j < 8; j++) acc[i][j] = 0.f;

    for (int k0 = 0; k0 < K; k0 += 8) {
        float4 av = *(const float4*)(Ap + k0);
        float4 wv = *(const float4*)(Wp + k0);
        As[lk + 0][lrow] = av.x; As[lk + 1][lrow] = av.y;
        As[lk + 2][lrow] = av.z; As[lk + 3][lrow] = av.w;
        Bs[lk + 0][lrow] = wv.x; Bs[lk + 1][lrow] = wv.y;
        Bs[lk + 2][lrow] = wv.z; Bs[lk + 3][lrow] = wv.w;
        __syncthreads();
#pragma unroll
        for (int kk = 0; kk < 8; kk++) {
            float a[8], b[8];
            float4 t0 = *(const float4*)&As[kk][ty * 4];
            float4 t1 = *(const float4*)&As[kk][64 + ty * 4];
            a[0] = t0.x; a[1] = t0.y; a[2] = t0.z; a[3] = t0.w;
            a[4] = t1.x; a[5] = t1.y; a[6] = t1.z; a[7] = t1.w;
            float4 u0 = *(const float4*)&Bs[kk][tx * 4];
            float4 u1 = *(const float4*)&Bs[kk][64 + tx * 4];
            b[0] = u0.x; b[1] = u0.y; b[2] = u0.z; b[3] = u0.w;
            b[4] = u1.x; b[5] = u1.y; b[6] = u1.z; b[7] = u1.w;
#pragma unroll
            for (int i = 0; i < 8; i++)
#pragma unroll
                for (int j = 0; j < 8; j++) acc[i][j] += a[i] * b[j];
        }
        __syncthreads();
    }

#pragma unroll
    for (int i = 0; i < 8; i++) {
        int m = m0 + ((i < 4) ? (ty * 4 + i) : (64 + ty * 4 + i - 4));
        float4 o0 = make_float4(acc[i][0], acc[i][1], acc[i][2], acc[i][3]);
        float4 o1 = make_float4(acc[i][4], acc[i][5], acc[i][6], acc[i][7]);
        *(float4*)&C[(size_t)m * N + n0 + tx * 4]      = o0;
        *(float4*)&C[(size_t)m * N + n0 + 64 + tx * 4] = o1;
    }
}

// ---------------------------------------------------------------------------
// RoPE in place: t layout [B*S, heads*64]. One thread per (row, head, j<32).
// ---------------------------------------------------------------------------
__global__ void rope_kernel(float* __restrict__ t, int heads, int total) {
    int idx = blockIdx.x * blockDim.x + threadIdx.x;
    if (idx >= total) return;
    int j = idx & 31;
    int h = (idx >> 5) % heads;
    int row = idx / (32 * heads);
    int s = row & (Ss - 1);
    // inv_freq = 10000^(-j/32)
    float inv = expf(-(float)j * (9.210340371976184f / 32.0f));
    float ang = (float)s * inv;
    float sn, cs;
    sincosf(ang, &sn, &cs);
    float* p = t + (size_t)row * (heads * HD) + h * HD;
    float x1 = p[j], x2 = p[j + 32];
    p[j]      = x1 * cs - x2 * sn;
    p[j + 32] = x2 * cs + x1 * sn;
}

// ---------------------------------------------------------------------------
// Flash attention, causal, GQA. Block = (q-tile of 64 rows, head, batch).
// KV tile = 32. 256 threads as 16x16; per thread: 4x2 scores, 4x4 O tile.
// ---------------------------------------------------------------------------
__global__ __launch_bounds__(256) void flash_kernel() {
    const int qt = blockIdx.x, h = blockIdx.y, b = blockIdx.z;
    const int qm0 = qt * 64;
    const int kvh = h / REP;
    __shared__ float Qs[64][65];
    __shared__ float Ks[32][65];
    __shared__ float Vs[32][68];
    __shared__ float Ps[64][33];
    const int tid = threadIdx.x;
    const int tx = tid & 15, ty = tid >> 4;

    // Load Q tile [64,64]
    const float* qbase = g_q + (size_t)(b * Ss + qm0) * (NH * HD) + h * HD;
#pragma unroll
    for (int i = 0; i < 4; i++) {
        int f = tid + i * 256;
        int r = f >> 4, c = (f & 15) << 2;
        float4 v = *(const float4*)(qbase + (size_t)r * (NH * HD) + c);
        Qs[r][c] = v.x; Qs[r][c + 1] = v.y; Qs[r][c + 2] = v.z; Qs[r][c + 3] = v.w;
    }

    float accO[4][4];
    float m_i[4], l_i[4];
#pragma unroll
    for (int ri = 0; ri < 4; ri++) {
        m_i[ri] = -1e30f; l_i[ri] = 0.f;
#pragma unroll
        for (int vi = 0; vi < 4; vi++) accO[ri][vi] = 0.f;
    }

    const float* kbase = g_k + (size_t)(b * Ss) * (NKV * HD) + kvh * HD;
    const float* vbase = g_v + (size_t)(b * Ss) * (NKV * HD) + kvh * HD;
    const int ntiles = 2 * qt + 2;

    for (int t = 0; t < ntiles; t++) {
        const int n0 = t * 32;
        // Load K/V tiles [32,64]
#pragma unroll
        for (int i = 0; i < 2; i++) {
            int f = tid + i * 256;
            int r = f >> 4, c = (f & 15) << 2;
            size_t off = (size_t)(n0 + r) * (NKV * HD) + c;
            float4 kq = *(const float4*)(kbase + off);
            float4 vq = *(const float4*)(vbase + off);
            Ks[r][c] = kq.x; Ks[r][c + 1] = kq.y; Ks[r][c + 2] = kq.z; Ks[r][c + 3] = kq.w;
            Vs[r][c] = vq.x; Vs[r][c + 1] = vq.y; Vs[r][c + 2] = vq.z; Vs[r][c + 3] = vq.w;
        }
        __syncthreads();

        // Scores: 4 rows x 2 cols per thread
        float sc[4][2];
#pragma unroll
        for (int ri = 0; ri < 4; ri++) { sc[ri][0] = 0.f; sc[ri][1] = 0.f; }
#pragma unroll 16
        for (int d = 0; d < 64; d++) {
            float k0 = Ks[tx * 2 + 0][d];
            float k1 = Ks[tx * 2 + 1][d];
#pragma unroll
            for (int ri = 0; ri < 4; ri++) {
                float qv = Qs[ty * 4 + ri][d];
                sc[ri][0] += qv * k0;
                sc[ri][1] += qv * k1;
            }
        }

        // Online softmax
#pragma unroll
        for (int ri = 0; ri < 4; ri++) {
            int gr = qm0 + ty * 4 + ri;
            float s0 = (n0 + tx * 2 + 0 > gr) ? -1e30f : sc[ri][0] * 0.125f;
            float s1 = (n0 + tx * 2 + 1 > gr) ? -1e30f : sc[ri][1] * 0.125f;
            float mx = fmaxf(s0, s1);
#pragma unroll
            for (int off = 8; off; off >>= 1)
                mx = fmaxf(mx, __shfl_xor_sync(0xffffffffu, mx, off));
            float mnew = fmaxf(m_i[ri], mx);
            float p0 = __expf(s0 - mnew), p1 = __expf(s1 - mnew);
            float rs = p0 + p1;
#pragma unroll
            for (int off = 8; off; off >>= 1)
                rs += __shfl_xor_sync(0xffffffffu, rs, off);
            float scl = __expf(m_i[ri] - mnew);
            l_i[ri] = l_i[ri] * scl + rs;
            m_i[ri] = mnew;
#pragma unroll
            for (int vi = 0; vi < 4; vi++) accO[ri][vi] *= scl;
            Ps[ty * 4 + ri][tx * 2 + 0] = p0;
            Ps[ty * 4 + ri][tx * 2 + 1] = p1;
        }
        __syncthreads();

        // O += P @ V
#pragma unroll 8
        for (int kv = 0; kv < 32; kv++) {
            float4 vv = *(const float4*)&Vs[kv][tx * 4];
#pragma unroll
            for (int ri = 0; ri < 4; ri++) {
                float p = Ps[ty * 4 + ri][kv];
                accO[ri][0] += p * vv.x;
                accO[ri][1] += p * vv.y;
                accO[ri][2] += p * vv.z;
                accO[ri][3] += p * vv.w;
            }
        }
        __syncthreads();
    }

    // Epilogue: normalize and write
    float* obase = g_o + (size_t)(b * Ss + qm0) * (NH * HD) + h * HD;
#pragma unroll
    for (int ri = 0; ri < 4; ri++) {
        float inv = 1.0f / l_i[ri];
        float4 o4 = make_float4(accO[ri][0] * inv, accO[ri][1] * inv,
                                accO[ri][2] * inv, accO[ri][3] * inv);
        *(float4*)(obase + (size_t)(ty * 4 + ri) * (NH * HD) + tx * 4) = o4;
    }
}

// ---------------------------------------------------------------------------
extern "C" void kernel_launch(void* const* d_in, const int* in_sizes, int n_in,
                              void* d_out, int out_size) {
    const float* x  = (const float*)d_in[0];
    const float* Wq = (const float*)d_in[1];
    const float* Wk = (const float*)d_in[2];
    const float* Wv = (const float*)d_in[3];
    const float* Wo = (const float*)d_in[4];
    float* out = (float*)d_out;

    float *q, *k, *v, *o;
    cudaGetSymbolAddress((void**)&q, g_q);
    cudaGetSymbolAddress((void**)&k, g_k);
    cudaGetSymbolAddress((void**)&v, g_v);
    cudaGetSymbolAddress((void**)&o, g_o);

    // Projections
    sgemm_nt<<<dim3(NH * HD / 128, MM / 128), 256>>>(x, Wq, q, MM, NH * HD, Dd);
    sgemm_nt<<<dim3(NKV * HD / 128, MM / 128), 256>>>(x, Wk, k, MM, NKV * HD, Dd);
    sgemm_nt<<<dim3(NKV * HD / 128, MM / 128), 256>>>(x, Wv, v, MM, NKV * HD, Dd);

    // RoPE on q and k
    {
        int total_q = MM * NH * 32;
        rope_kernel<<<(total_q + 255) / 256, 256>>>(q, NH, total_q);
        int total_k = MM * NKV * 32;
        rope_kernel<<<(total_k + 255) / 256, 256>>>(k, NKV, total_k);
    }

    // Attention
    flash_kernel<<<dim3(Ss / 64, NH, Bb), 256>>>();

    // Output projection
    sgemm_nt<<<dim3(Dd / 128, MM / 128), 256>>>(o, Wo, out, MM, Dd, NH * HD);
}

// round 3
// speedup vs baseline: 6.9808x; 6.9808x over previous
#include <cuda_runtime.h>
#include <cuda_fp16.h>
#include <cstdint>
#include <math.h>

#define Bb 2
#define Ss 2048
#define Dd 1024
#define NH 16
#define NKV 4
#define HD 64
#define MM (Bb*Ss)

// ---------------- scratch (__device__ globals; no allocation allowed) ------
__device__ __align__(16) __half g_xh [MM * Dd];        // x fp16
__device__ __align__(16) __half g_wh [1536 * Dd];      // Wq;Wk;Wv fp16 stacked
__device__ __align__(16) __half g_woh[Dd * 1024];      // Wo fp16
__device__ __align__(16) float  g_qkv[MM * 1536];      // qkv fp32
__device__ __align__(16) __half g_qh [Bb*NH *Ss*HD];   // [B][NH][S][HD], pre-scaled
__device__ __align__(16) __half g_kh [Bb*NKV*Ss*HD];   // [B][NKV][S][HD]
__device__ __align__(16) __half g_vh [Bb*NKV*Ss*HD];   // [B][NKV][S][HD]
__device__ __align__(16) __half g_oh [MM * NH*HD];     // attn out fp16

// ---------------- warp-MMA helpers (baseline PTX, valid on compute_103) ----
__device__ __forceinline__ uint32_t smem_u32(const void* p) {
    uint32_t a;
    asm("{ .reg .u64 t; cvta.to.shared.u64 t, %1; cvt.u32.u64 %0, t; }" : "=r"(a) : "l"(p));
    return a;
}
__device__ __forceinline__ void mma16816(float* c, const uint32_t* a, const uint32_t* b) {
    asm volatile("mma.sync.aligned.m16n8k16.row.col.f32.f16.f16.f32 "
                 "{%0,%1,%2,%3}, {%4,%5,%6,%7}, {%8,%9}, {%0,%1,%2,%3};"
                 : "+f"(c[0]), "+f"(c[1]), "+f"(c[2]), "+f"(c[3])
                 : "r"(a[0]), "r"(a[1]), "r"(a[2]), "r"(a[3]), "r"(b[0]), "r"(b[1]));
}
__device__ __forceinline__ void ldsm_x4(uint32_t* r, uint32_t a) {
    asm volatile("ldmatrix.sync.aligned.m8n8.x4.shared.b16 {%0,%1,%2,%3}, [%4];"
                 : "=r"(r[0]), "=r"(r[1]), "=r"(r[2]), "=r"(r[3]) : "r"(a));
}
__device__ __forceinline__ void ldsm_x2(uint32_t* r, uint32_t a) {
    asm volatile("ldmatrix.sync.aligned.m8n8.x2.shared.b16 {%0,%1}, [%2];"
                 : "=r"(r[0]), "=r"(r[1]) : "r"(a));
}
__device__ __forceinline__ void ldsm_x2t(uint32_t* r, uint32_t a) {
    asm volatile("ldmatrix.sync.aligned.m8n8.x2.trans.shared.b16 {%0,%1}, [%2];"
                 : "=r"(r[0]), "=r"(r[1]) : "r"(a));
}
__device__ __forceinline__ uint32_t packh2(float x, float y) {
    __half2 h = __floats2half2_rn(x, y);
    return *reinterpret_cast<uint32_t*>(&h);
}

// ---------------- fp32 -> fp16 convert -------------------------------------
__global__ void f2h(const float* __restrict__ s, __half* __restrict__ d, int n4) {
    int i = blockIdx.x * blockDim.x + threadIdx.x;
    if (i < n4) {
        float4 v = ((const float4*)s)[i];
        ((__half2*)d)[2 * i + 0] = __floats2half2_rn(v.x, v.y);
        ((__half2*)d)[2 * i + 1] = __floats2half2_rn(v.z, v.w);
    }
}

// ---------------- HMMA GEMM: C[M,N] = A[M,K]*B[N,K]^T, fp16 in fp32 out ----
// grid(N/128, M/128), 256 threads (8 warps, 2M x 4N), BK=32, double-buffered.
#define AST 40   // smem row stride in halves (80B: conflict-free for ldmatrix)
__global__ __launch_bounds__(256) void gemm_f16(const __half* __restrict__ A,
                                                const __half* __restrict__ B,
                                                float* __restrict__ C,
                                                int N, int K) {
    __shared__ __align__(16) __half As[2][128 * AST];
    __shared__ __align__(16) __half Bs[2][128 * AST];
    const int tid = threadIdx.x, lane = tid & 31, wid = tid >> 5;
    const int wm = wid & 1, wn = wid >> 1;
    const int m0 = blockIdx.y * 128, n0 = blockIdx.x * 128;
    const int gid = lane >> 2, tig = lane & 3;

    float acc[4][4][4];
#pragma unroll
    for (int mi = 0; mi < 4; mi++)
#pragma unroll
        for (int ni = 0; ni < 4; ni++)
#pragma unroll
            for (int j = 0; j < 4; j++) acc[mi][ni][j] = 0.f;

    // per-thread chunks: 512 16B chunks per tile per operand -> 2 each
    const int r0c = tid >> 2, c0c = tid & 3;
    const int r1c = (tid + 256) >> 2, c1c = (tid + 256) & 3;

    const int NKt = K >> 5;
    // prologue: tile 0
    *(uint4*)&As[0][r0c * AST + c0c * 8] = *(const uint4*)(A + (size_t)(m0 + r0c) * K + c0c * 8);
    *(uint4*)&As[0][r1c * AST + c1c * 8] = *(const uint4*)(A + (size_t)(m0 + r1c) * K + c1c * 8);
    *(uint4*)&Bs[0][r0c * AST + c0c * 8] = *(const uint4*)(B + (size_t)(n0 + r0c) * K + c0c * 8);
    *(uint4*)&Bs[0][r1c * AST + c1c * 8] = *(const uint4*)(B + (size_t)(n0 + r1c) * K + c1c * 8);
    __syncthreads();

    const uint32_t asb0 = smem_u32(As), bsb0 = smem_u32(Bs);
    for (int kt = 0; kt < NKt; kt++) {
        const int buf = kt & 1;
        uint4 pa0, pa1, pb0, pb1;
        if (kt + 1 < NKt) {
            const int k0 = (kt + 1) << 5;
            pa0 = *(const uint4*)(A + (size_t)(m0 + r0c) * K + k0 + c0c * 8);
            pa1 = *(const uint4*)(A + (size_t)(m0 + r1c) * K + k0 + c1c * 8);
            pb0 = *(const uint4*)(B + (size_t)(n0 + r0c) * K + k0 + c0c * 8);
            pb1 = *(const uint4*)(B + (size_t)(n0 + r1c) * K + k0 + c1c * 8);
        }
        const uint32_t asb = asb0 + buf * (128 * AST * 2);
        const uint32_t bsb = bsb0 + buf * (128 * AST * 2);
#pragma unroll
        for (int ks = 0; ks < 2; ks++) {
            uint32_t af[4][4];
#pragma unroll
            for (int mi = 0; mi < 4; mi++)
                ldsm_x4(af[mi], asb + (((wm * 64 + mi * 16 + (lane & 15)) * AST
                                        + ks * 16 + (lane >> 4) * 8) << 1));
#pragma unroll
            for (int ni = 0; ni < 4; ni++) {
                uint32_t bf[2];
                ldsm_x2(bf, bsb + (((wn * 32 + ni * 8 + (lane & 7)) * AST
                                    + ks * 16 + ((lane >> 3) & 1) * 8) << 1));
#pragma unroll
                for (int mi = 0; mi < 4; mi++) mma16816(acc[mi][ni], af[mi], bf);
            }
        }
        if (kt + 1 < NKt) {
            const int nb = buf ^ 1;
            *(uint4*)&As[nb][r0c * AST + c0c * 8] = pa0;
            *(uint4*)&As[nb][r1c * AST + c1c * 8] = pa1;
            *(uint4*)&Bs[nb][r0c * AST + c0c * 8] = pb0;
            *(uint4*)&Bs[nb][r1c * AST + c1c * 8] = pb1;
        }
        __syncthreads();
    }

#pragma unroll
    for (int mi = 0; mi < 4; mi++)
#pragma unroll
        for (int ni = 0; ni < 4; ni++) {
            const int row = m0 + wm * 64 + mi * 16 + gid;
            const int col = n0 + wn * 32 + ni * 8 + tig * 2;
            *(float2*)&C[(size_t)row * N + col]       = make_float2(acc[mi][ni][0], acc[mi][ni][1]);
            *(float2*)&C[(size_t)(row + 8) * N + col] = make_float2(acc[mi][ni][2], acc[mi][ni][3]);
        }
}

// ---------------- RoPE + layout --------------------------------------------
__global__ void rope_q(const float* __restrict__ qkv) {
    int idx = blockIdx.x * blockDim.x + threadIdx.x;
    if (idx >= MM * NH * 32) return;
    int j = idx & 31, hh = (idx >> 5) & 15, row = idx >> 9;
    int s = row & (Ss - 1), b = row >> 11;
    float ang = (float)s * expf(-(float)j * (9.210340371976184f / 32.f));
    float sn, cs; sincosf(ang, &sn, &cs);
    const float* p = qkv + (size_t)row * 1536 + hh * 64;
    float x1 = p[j], x2 = p[j + 32];
    __half* o = g_qh + ((size_t)(b * NH + hh) * Ss + s) * HD;
    o[j]      = __float2half((x1 * cs - x2 * sn) * 0.125f);
    o[j + 32] = __float2half((x2 * cs + x1 * sn) * 0.125f);
}
__global__ void rope_k(const float* __restrict__ qkv) {
    int idx = blockIdx.x * blockDim.x + threadIdx.x;
    if (idx >= MM * NKV * 32) return;
    int j = idx & 31, hh = (idx >> 5) & 3, row = idx >> 7;
    int s = row & (Ss - 1), b = row >> 11;
    float ang = (float)s * expf(-(float)j * (9.210340371976184f / 32.f));
    float sn, cs; sincosf(ang, &sn, &cs);
    const float* p = qkv + (size_t)row * 1536 + 1024 + hh * 64;
    float x1 = p[j], x2 = p[j + 32];
    __half* o = g_kh + ((size_t)(b * NKV + hh) * Ss + s) * HD;
    o[j]      = __float2half(x1 * cs - x2 * sn);
    o[j + 32] = __float2half(x2 * cs + x1 * sn);
}
__global__ void conv_v(const float* __restrict__ qkv) {
    int idx = blockIdx.x * blockDim.x + threadIdx.x;
    if (idx >= MM * NKV * 16) return;
    int d4 = idx & 15, hh = (idx >> 4) & 3, row = idx >> 6;
    int s = row & (Ss - 1), b = row >> 11;
    float4 v = *(const float4*)(qkv + (size_t)row * 1536 + 1280 + hh * 64 + d4 * 4);
    __half2* o = (__half2*)(g_vh + ((size_t)(b * NKV + hh) * Ss + s) * HD + d4 * 4);
    o[0] = __floats2half2_rn(v.x, v.y);
    o[1] = __floats2half2_rn(v.z, v.w);
}

// ---------------- flash attention (HMMA) ------------------------------------
// grid(32, NH, Bb), 128 threads (4 warps x 16 q-rows), KV tile 64.
#define FST 72   // smem row stride in halves (144B: conflict-free)
__global__ __launch_bounds__(128) void flash_f16() {
    __shared__ __align__(16) __half Qs[64 * FST];
    __shared__ __align__(16) __half Ks[64 * FST];
    __shared__ __align__(16) __half Vs[64 * FST];
    const int tid = threadIdx.x, lane = tid & 31, w = tid >> 5;
    const int qt = blockIdx.x, h = blockIdx.y, b = blockIdx.z;
    const int qm0 = qt * 64, kvh = h >> 2, qw0 = w * 16;
    const int gid = lane >> 2, tig = lane & 3;

    const __half* qb = g_qh + ((size_t)(b * NH + h) * Ss + qm0) * HD;
#pragma unroll
    for (int i = 0; i < 4; i++) {
        int u = tid + i * 128, r = u >> 3, c = u & 7;
        *(uint4*)&Qs[r * FST + c * 8] = *(const uint4*)(qb + (size_t)r * HD + c * 8);
    }
    __syncthreads();

    const uint32_t qsb = smem_u32(Qs), ksb = smem_u32(Ks), vsb = smem_u32(Vs);
    uint32_t aQ[4][4];
#pragma unroll
    for (int ks = 0; ks < 4; ks++)
        ldsm_x4(aQ[ks], qsb + (((qw0 + (lane & 15)) * FST + ks * 16 + (lane >> 4) * 8) << 1));

    const __half* kb = g_kh + (size_t)(b * NKV + kvh) * Ss * HD;
    const __half* vb = g_vh + (size_t)(b * NKV + kvh) * Ss * HD;

    float oacc[8][4];
#pragma unroll
    for (int ni = 0; ni < 8; ni++)
#pragma unroll
        for (int j = 0; j < 4; j++) oacc[ni][j] = 0.f;
    float m0_ = -1e30f, m1_ = -1e30f, l0_ = 0.f, l1_ = 0.f;

    const int last = qm0 >> 6;
    for (int t = 0; t <= last; t++) {
        const int n0 = t * 64;
#pragma unroll
        for (int i = 0; i < 8; i++) {
            int u = tid + i * 128, r = u >> 3, c = u & 7;
            if (i < 4) *(uint4*)&Ks[r * FST + c * 8] = *(const uint4*)(kb + (size_t)(n0 + r) * HD + c * 8);
            else       *(uint4*)&Vs[(r - 64) * FST + c * 8] = *(const uint4*)(vb + (size_t)(n0 + r - 64) * HD + c * 8);
        }
        __syncthreads();

        float sacc[8][4];
#pragma unroll
        for (int ni = 0; ni < 8; ni++)
#pragma unroll
            for (int j = 0; j < 4; j++) sacc[ni][j] = 0.f;
#pragma unroll
        for (int ks = 0; ks < 4; ks++)
#pragma unroll
            for (int ni = 0; ni < 8; ni++) {
                uint32_t bf[2];
                ldsm_x2(bf, ksb + (((ni * 8 + (lane & 7)) * FST + ks * 16 + ((lane >> 3) & 1) * 8) << 1));
                mma16816(sacc[ni], aQ[ks], bf);
            }

        if (t == last) {
            const int row0 = qm0 + qw0 + gid, row1 = row0 + 8;
#pragma unroll
            for (int ni = 0; ni < 8; ni++) {
                const int col = n0 + ni * 8 + tig * 2;
                if (col     > row0) sacc[ni][0] = -1e30f;
                if (col + 1 > row0) sacc[ni][1] = -1e30f;
                if (col     > row1) sacc[ni][2] = -1e30f;
                if (col + 1 > row1) sacc[ni][3] = -1e30f;
            }
        }

        float mx0 = -1e30f, mx1 = -1e30f;
#pragma unroll
        for (int ni = 0; ni < 8; ni++) {
            mx0 = fmaxf(mx0, fmaxf(sacc[ni][0], sacc[ni][1]));
            mx1 = fmaxf(mx1, fmaxf(sacc[ni][2], sacc[ni][3]));
        }
        mx0 = fmaxf(mx0, __shfl_xor_sync(0xffffffffu, mx0, 1));
        mx0 = fmaxf(mx0, __shfl_xor_sync(0xffffffffu, mx0, 2));
        mx1 = fmaxf(mx1, __shfl_xor_sync(0xffffffffu, mx1, 1));
        mx1 = fmaxf(mx1, __shfl_xor_sync(0xffffffffu, mx1, 2));
        const float mn0 = fmaxf(m0_, mx0), mn1 = fmaxf(m1_, mx1);
        const float al0 = __expf(m0_ - mn0), al1 = __expf(m1_ - mn1);
        float s0 = 0.f, s1 = 0.f;
#pragma unroll
        for (int ni = 0; ni < 8; ni++) {
            sacc[ni][0] = __expf(sacc[ni][0] - mn0);
            sacc[ni][1] = __expf(sacc[ni][1] - mn0);
            sacc[ni][2] = __expf(sacc[ni][2] - mn1);
            sacc[ni][3] = __expf(sacc[ni][3] - mn1);
            s0 += sacc[ni][0] + sacc[ni][1];
            s1 += sacc[ni][2] + sacc[ni][3];
        }
        s0 += __shfl_xor_sync(0xffffffffu, s0, 1);
        s0 += __shfl_xor_sync(0xffffffffu, s0, 2);
        s1 += __shfl_xor_sync(0xffffffffu, s1, 1);
        s1 += __shfl_xor_sync(0xffffffffu, s1, 2);
        l0_ = l0_ * al0 + s0; l1_ = l1_ * al1 + s1;
        m0_ = mn0; m1_ = mn1;

        uint32_t aP[4][4];
#pragma unroll
        for (int ks = 0; ks < 4; ks++) {
            aP[ks][0] = packh2(sacc[2 * ks][0],     sacc[2 * ks][1]);
            aP[ks][1] = packh2(sacc[2 * ks][2],     sacc[2 * ks][3]);
            aP[ks][2] = packh2(sacc[2 * ks + 1][0], sacc[2 * ks + 1][1]);
            aP[ks][3] = packh2(sacc[2 * ks + 1][2], sacc[2 * ks + 1][3]);
        }
#pragma unroll
        for (int ni = 0; ni < 8; ni++) {
            oacc[ni][0] *= al0; oacc[ni][1] *= al0;
            oacc[ni][2] *= al1; oacc[ni][3] *= al1;
        }
#pragma unroll
        for (int ks = 0; ks < 4; ks++)
#pragma unroll
            for (int ni = 0; ni < 8; ni++) {
                uint32_t bf[2];
                ldsm_x2t(bf, vsb + (((ks * 16 + (lane & 15)) * FST + ni * 8) << 1));
                mma16816(oacc[ni], aP[ks], bf);
            }
        __syncthreads();
    }

    const float inv0 = 1.f / l0_, inv1 = 1.f / l1_;
    __half* ob = g_oh + (size_t)(b * Ss + qm0 + qw0) * (NH * HD) + h * HD;
#pragma unroll
    for (int ni = 0; ni < 8; ni++) {
        const int col = ni * 8 + tig * 2;
        __half2 o0 = __floats2half2_rn(oacc[ni][0] * inv0, oacc[ni][1] * inv0);
        __half2 o1 = __floats2half2_rn(oacc[ni][2] * inv1, oacc[ni][3] * inv1);
        *(__half2*)&ob[(size_t)gid * (NH * HD) + col]       = o0;
        *(__half2*)&ob[(size_t)(gid + 8) * (NH * HD) + col] = o1;
    }
}

// ---------------------------------------------------------------------------
extern "C" void kernel_launch(void* const* d_in, const int* in_sizes, int n_in,
                              void* d_out, int out_size) {
    const float* x  = (const float*)d_in[0];
    const float* Wq = (const float*)d_in[1];
    const float* Wk = (const float*)d_in[2];
    const float* Wv = (const float*)d_in[3];
    const float* Wo = (const float*)d_in[4];
    float* out = (float*)d_out;

    __half *xh, *wh, *woh, *oh;
    float* qkv;
    cudaGetSymbolAddress((void**)&xh,  g_xh);
    cudaGetSymbolAddress((void**)&wh,  g_wh);
    cudaGetSymbolAddress((void**)&woh, g_woh);
    cudaGetSymbolAddress((void**)&qkv, g_qkv);
    cudaGetSymbolAddress((void**)&oh,  g_oh);

    // fp32 -> fp16 (Wq/Wk/Wv stacked into one [1536,1024] weight)
    f2h<<<(MM * Dd / 4 + 255) / 256, 256>>>(x, xh, MM * Dd / 4);
    f2h<<<(1024 * 1024 / 4 + 255) / 256, 256>>>(Wq, wh, 1024 * 1024 / 4);
    f2h<<<(256 * 1024 / 4 + 255) / 256, 256>>>(Wk, wh + 1024 * 1024, 256 * 1024 / 4);
    f2h<<<(256 * 1024 / 4 + 255) / 256, 256>>>(Wv, wh + 1280 * 1024, 256 * 1024 / 4);
    f2h<<<(1024 * 1024 / 4 + 255) / 256, 256>>>(Wo, woh, 1024 * 1024 / 4);

    // fused QKV projection: [4096,1536] = x * Wqkv^T
    gemm_f16<<<dim3(12, 32), 256>>>(xh, wh, qkv, 1536, 1024);

    // RoPE (q pre-scaled by 1/8) + V layout
    rope_q<<<(MM * NH * 32 + 255) / 256, 256>>>(qkv);
    rope_k<<<(MM * NKV * 32 + 255) / 256, 256>>>(qkv);
    conv_v<<<(MM * NKV * 16 + 255) / 256, 256>>>(qkv);

    // attention
    flash_f16<<<dim3(32, NH, Bb), 128>>>();

    // output projection: out = o * Wo^T
    gemm_f16<<<dim3(8, 32), 256>>>(oh, woh, out, 1024, 1024);
}